// round 1
// baseline (speedup 1.0000x reference)
#include <cuda_runtime.h>

#define SEQ    1024
#define BATCH  4
#define DMODEL 1024
#define NH     16
#define DK     64
#define DV     64
#define DOUT   1024
#define ROWS   (SEQ * BATCH)      // 4096
#define HB     (NH * BATCH)       // 64

// Scratch (no allocation allowed): q, k, v, ctx as (ROWS x 1024) row-major,
// row = s*BATCH + b, col = h*64 + d.
__device__ float g_q[ROWS * NH * DK];
__device__ float g_k[ROWS * NH * DK];
__device__ float g_v[ROWS * NH * DV];
__device__ float g_ctx[ROWS * NH * DV];

// ---------------------------------------------------------------------------
// Generic SGEMM + bias: C[M x N] = A[M x K] @ B[K x N] + bias[N]
// A, B, C contiguous row-major. BM=BN=64, BK=16, 256 threads, 4x4 microtile.
// ---------------------------------------------------------------------------
__global__ __launch_bounds__(256) void sgemm_bias(
    const float* __restrict__ A, const float* __restrict__ B,
    const float* __restrict__ bias, float* __restrict__ C,
    int M, int N, int K)
{
    __shared__ float As[16][65];   // [k][m], padded
    __shared__ float Bs[16][64];   // [k][n]

    const int tid = threadIdx.x;
    const int bm = blockIdx.y * 64;
    const int bn = blockIdx.x * 64;
    const int tx = tid & 15;
    const int ty = tid >> 4;

    float acc[4][4] = {};

    for (int k0 = 0; k0 < K; k0 += 16) {
        {   // A tile: 64 rows x 16 k
            int r = tid >> 2;
            int c = (tid & 3) << 2;
            float4 av = *reinterpret_cast<const float4*>(
                A + (size_t)(bm + r) * K + k0 + c);
            As[c + 0][r] = av.x; As[c + 1][r] = av.y;
            As[c + 2][r] = av.z; As[c + 3][r] = av.w;
        }
        {   // B tile: 16 k x 64 cols
            int r = tid >> 4;
            int c = (tid & 15) << 2;
            *reinterpret_cast<float4*>(&Bs[r][c]) =
                *reinterpret_cast<const float4*>(B + (size_t)(k0 + r) * N + bn + c);
        }
        __syncthreads();

        #pragma unroll
        for (int kk = 0; kk < 16; kk++) {
            float a0 = As[kk][ty * 4 + 0];
            float a1 = As[kk][ty * 4 + 1];
            float a2 = As[kk][ty * 4 + 2];
            float a3 = As[kk][ty * 4 + 3];
            float4 bv = *reinterpret_cast<const float4*>(&Bs[kk][tx * 4]);
            acc[0][0] += a0 * bv.x; acc[0][1] += a0 * bv.y;
            acc[0][2] += a0 * bv.z; acc[0][3] += a0 * bv.w;
            acc[1][0] += a1 * bv.x; acc[1][1] += a1 * bv.y;
            acc[1][2] += a1 * bv.z; acc[1][3] += a1 * bv.w;
            acc[2][0] += a2 * bv.x; acc[2][1] += a2 * bv.y;
            acc[2][2] += a2 * bv.z; acc[2][3] += a2 * bv.w;
            acc[3][0] += a3 * bv.x; acc[3][1] += a3 * bv.y;
            acc[3][2] += a3 * bv.z; acc[3][3] += a3 * bv.w;
        }
        __syncthreads();
    }

    #pragma unroll
    for (int i = 0; i < 4; i++) {
        int row = bm + ty * 4 + i;
        #pragma unroll
        for (int j = 0; j < 4; j++) {
            int col = bn + tx * 4 + j;
            C[(size_t)row * N + col] = acc[i][j] + bias[col];
        }
    }
}

// ---------------------------------------------------------------------------
// Logits: per (h,b): L[s,t] = (q_hb[s,:] . k_hb[t,:]) / 8 written to attn.
// q/k rows are strided: element (s, d) at base + s*4096 + d, base = b*1024+h*64.
// Block computes a 64x64 tile of one (h,b). grid = (16, 16, 64).
// ---------------------------------------------------------------------------
__global__ __launch_bounds__(256) void logits_kernel(float* __restrict__ attn)
{
    __shared__ float Qs[64][65];
    __shared__ float Ks[64][65];

    const int tid = threadIdx.x;
    const int hb = blockIdx.z;          // h*BATCH + b
    const int h = hb >> 2;
    const int b = hb & 3;
    const int s0 = blockIdx.y * 64;
    const int t0 = blockIdx.x * 64;

    const float* qbase = g_q + (size_t)b * 1024 + h * 64;
    const float* kbase = g_k + (size_t)b * 1024 + h * 64;

    #pragma unroll
    for (int it = 0; it < 4; it++) {
        int f = it * 256 + tid;       // float4 index over 64x16
        int r = f >> 4;
        int c = (f & 15) << 2;
        float4 qv = *reinterpret_cast<const float4*>(qbase + (size_t)(s0 + r) * 4096 + c);
        Qs[r][c + 0] = qv.x; Qs[r][c + 1] = qv.y; Qs[r][c + 2] = qv.z; Qs[r][c + 3] = qv.w;
        float4 kv = *reinterpret_cast<const float4*>(kbase + (size_t)(t0 + r) * 4096 + c);
        Ks[r][c + 0] = kv.x; Ks[r][c + 1] = kv.y; Ks[r][c + 2] = kv.z; Ks[r][c + 3] = kv.w;
    }
    __syncthreads();

    const int tx = tid & 15;
    const int ty = tid >> 4;
    float acc[4][4] = {};

    #pragma unroll
    for (int d = 0; d < 64; d++) {
        float a0 = Qs[ty * 4 + 0][d];
        float a1 = Qs[ty * 4 + 1][d];
        float a2 = Qs[ty * 4 + 2][d];
        float a3 = Qs[ty * 4 + 3][d];
        float b0 = Ks[tx * 4 + 0][d];
        float b1 = Ks[tx * 4 + 1][d];
        float b2 = Ks[tx * 4 + 2][d];
        float b3 = Ks[tx * 4 + 3][d];
        acc[0][0] += a0 * b0; acc[0][1] += a0 * b1; acc[0][2] += a0 * b2; acc[0][3] += a0 * b3;
        acc[1][0] += a1 * b0; acc[1][1] += a1 * b1; acc[1][2] += a1 * b2; acc[1][3] += a1 * b3;
        acc[2][0] += a2 * b0; acc[2][1] += a2 * b1; acc[2][2] += a2 * b2; acc[2][3] += a2 * b3;
        acc[3][0] += a3 * b0; acc[3][1] += a3 * b1; acc[3][2] += a3 * b2; acc[3][3] += a3 * b3;
    }

    float* out = attn + ((size_t)hb * 1024 + s0) * 1024 + t0;
    const float scale = 0.125f;   // 1/sqrt(64)
    #pragma unroll
    for (int i = 0; i < 4; i++)
        #pragma unroll
        for (int j = 0; j < 4; j++)
            out[(size_t)(ty * 4 + i) * 1024 + tx * 4 + j] = acc[i][j] * scale;
}

// ---------------------------------------------------------------------------
// In-place row softmax over 1024 elements. One block (256 threads) per row.
// ---------------------------------------------------------------------------
__global__ __launch_bounds__(256) void softmax_kernel(float* __restrict__ attn)
{
    float* p = attn + (size_t)blockIdx.x * 1024;
    const int tid = threadIdx.x;

    float4 v = *reinterpret_cast<const float4*>(p + tid * 4);
    float m = fmaxf(fmaxf(v.x, v.y), fmaxf(v.z, v.w));
    #pragma unroll
    for (int o = 16; o; o >>= 1) m = fmaxf(m, __shfl_xor_sync(0xffffffffu, m, o));

    __shared__ float red[8];
    if ((tid & 31) == 0) red[tid >> 5] = m;
    __syncthreads();
    float bm = red[0];
    #pragma unroll
    for (int w = 1; w < 8; w++) bm = fmaxf(bm, red[w]);

    v.x = __expf(v.x - bm); v.y = __expf(v.y - bm);
    v.z = __expf(v.z - bm); v.w = __expf(v.w - bm);
    float s = (v.x + v.y) + (v.z + v.w);
    #pragma unroll
    for (int o = 16; o; o >>= 1) s += __shfl_xor_sync(0xffffffffu, s, o);

    __syncthreads();
    if ((tid & 31) == 0) red[tid >> 5] = s;
    __syncthreads();
    float tot = ((red[0] + red[1]) + (red[2] + red[3])) +
                ((red[4] + red[5]) + (red[6] + red[7]));
    float inv = 1.0f / tot;

    v.x *= inv; v.y *= inv; v.z *= inv; v.w *= inv;
    *reinterpret_cast<float4*>(p + tid * 4) = v;
}

// ---------------------------------------------------------------------------
// ctx = attn_hb (1024 x 1024) @ v_hb (1024 x 64), v strided like q/k.
// Block: 64 s-rows x all 64 dv cols. grid = (1, 16, 64).
// ---------------------------------------------------------------------------
__global__ __launch_bounds__(256) void av_kernel(const float* __restrict__ attn)
{
    __shared__ float Ps[16][65];   // [k][m]
    __shared__ float Vs[16][64];   // [k][n]

    const int tid = threadIdx.x;
    const int hb = blockIdx.z;
    const int h = hb >> 2;
    const int b = hb & 3;
    const int s0 = blockIdx.y * 64;

    const float* P = attn + (size_t)hb * 1024 * 1024;
    const float* vbase = g_v + (size_t)b * 1024 + h * 64;

    const int tx = tid & 15;
    const int ty = tid >> 4;
    float acc[4][4] = {};

    for (int k0 = 0; k0 < 1024; k0 += 16) {
        {   // P tile 64 x 16
            int r = tid >> 2;
            int c = (tid & 3) << 2;
            float4 pv = *reinterpret_cast<const float4*>(
                P + (size_t)(s0 + r) * 1024 + k0 + c);
            Ps[c + 0][r] = pv.x; Ps[c + 1][r] = pv.y;
            Ps[c + 2][r] = pv.z; Ps[c + 3][r] = pv.w;
        }
        {   // V tile 16 x 64 (strided rows)
            int r = tid >> 4;
            int c = (tid & 15) << 2;
            *reinterpret_cast<float4*>(&Vs[r][c]) =
                *reinterpret_cast<const float4*>(vbase + (size_t)(k0 + r) * 4096 + c);
        }
        __syncthreads();

        #pragma unroll
        for (int kk = 0; kk < 16; kk++) {
            float a0 = Ps[kk][ty * 4 + 0];
            float a1 = Ps[kk][ty * 4 + 1];
            float a2 = Ps[kk][ty * 4 + 2];
            float a3 = Ps[kk][ty * 4 + 3];
            float4 bv = *reinterpret_cast<const float4*>(&Vs[kk][tx * 4]);
            acc[0][0] += a0 * bv.x; acc[0][1] += a0 * bv.y;
            acc[0][2] += a0 * bv.z; acc[0][3] += a0 * bv.w;
            acc[1][0] += a1 * bv.x; acc[1][1] += a1 * bv.y;
            acc[1][2] += a1 * bv.z; acc[1][3] += a1 * bv.w;
            acc[2][0] += a2 * bv.x; acc[2][1] += a2 * bv.y;
            acc[2][2] += a2 * bv.z; acc[2][3] += a2 * bv.w;
            acc[3][0] += a3 * bv.x; acc[3][1] += a3 * bv.y;
            acc[3][2] += a3 * bv.z; acc[3][3] += a3 * bv.w;
        }
        __syncthreads();
    }

    float* cbase = g_ctx + (size_t)b * 1024 + h * 64;
    #pragma unroll
    for (int i = 0; i < 4; i++)
        #pragma unroll
        for (int j = 0; j < 4; j++)
            cbase[(size_t)(s0 + ty * 4 + i) * 4096 + tx * 4 + j] = acc[i][j];
}

// ---------------------------------------------------------------------------
extern "C" void kernel_launch(void* const* d_in, const int* in_sizes, int n_in,
                              void* d_out, int out_size)
{
    const float* query = (const float*)d_in[0];
    const float* key_  = (const float*)d_in[1];
    const float* value = (const float*)d_in[2];
    const float* Wq = (const float*)d_in[3];
    const float* bq = (const float*)d_in[4];
    const float* Wk = (const float*)d_in[5];
    const float* bk = (const float*)d_in[6];
    const float* Wv = (const float*)d_in[7];
    const float* bv = (const float*)d_in[8];
    const float* Wo = (const float*)d_in[9];
    const float* bo = (const float*)d_in[10];

    float* out  = (float*)d_out;                       // (S, B, D_OUT)
    float* attn = out + (size_t)ROWS * DOUT;           // (H, B, S, S)

    float *q, *k, *v, *ctx;
    cudaGetSymbolAddress((void**)&q,   g_q);
    cudaGetSymbolAddress((void**)&k,   g_k);
    cudaGetSymbolAddress((void**)&v,   g_v);
    cudaGetSymbolAddress((void**)&ctx, g_ctx);

    dim3 gProj(DMODEL / 64, ROWS / 64);                // (16, 64)
    sgemm_bias<<<gProj, 256>>>(query, Wq, bq, q, ROWS, NH * DK, DMODEL);
    sgemm_bias<<<gProj, 256>>>(key_,  Wk, bk, k, ROWS, NH * DK, DMODEL);
    sgemm_bias<<<gProj, 256>>>(value, Wv, bv, v, ROWS, NH * DV, DMODEL);

    dim3 gLog(SEQ / 64, SEQ / 64, HB);                 // (16, 16, 64)
    logits_kernel<<<gLog, 256>>>(attn);

    softmax_kernel<<<HB * SEQ, 256>>>(attn);           // 65536 rows

    dim3 gAv(1, SEQ / 64, HB);                         // (1, 16, 64)
    av_kernel<<<gAv, 256>>>(attn);

    sgemm_bias<<<gProj, 256>>>(ctx, Wo, bo, out, ROWS, DOUT, DMODEL);
}

// round 4
// speedup vs baseline: 1.7974x; 1.7974x over previous
#include <cuda_runtime.h>
#include <cuda_bf16.h>
#include <cstdint>

#define SEQ    1024
#define BATCH  4
#define DMODEL 1024
#define NH     16
#define DK     64
#define DV     64
#define DOUT   1024
#define ROWS   (SEQ * BATCH)      // 4096
#define HB     (NH * BATCH)       // 64

typedef __nv_bfloat16 bf16;

// input splits: [ROWS][1024] hi/lo
__device__ bf16 s_qi_h[ROWS * DMODEL], s_qi_l[ROWS * DMODEL];
__device__ bf16 s_ki_h[ROWS * DMODEL], s_ki_l[ROWS * DMODEL];
__device__ bf16 s_vi_h[ROWS * DMODEL], s_vi_l[ROWS * DMODEL];
// transposed weight splits: [N][K]
__device__ bf16 s_w_h[4][DMODEL * DMODEL], s_w_l[4][DMODEL * DMODEL];
// per-head projections: q,k: [hb][s][64]; vt: [hb][dv][s]
__device__ bf16 g_qh[HB * SEQ * DK], g_ql[HB * SEQ * DK];
__device__ bf16 g_kh[HB * SEQ * DK], g_kl[HB * SEQ * DK];
__device__ bf16 g_vth[HB * DV * SEQ], g_vtl[HB * DV * SEQ];
// context splits: [ROWS][1024]
__device__ bf16 g_cth[ROWS * DMODEL], g_ctl[ROWS * DMODEL];

// m16n8k16 bf16 mma, fp32 accum
__device__ __forceinline__ void mma_bf16(float* c,
    uint32_t a0, uint32_t a1, uint32_t a2, uint32_t a3, uint32_t b0, uint32_t b1)
{
    asm volatile(
        "mma.sync.aligned.m16n8k16.row.col.f32.bf16.bf16.f32 "
        "{%0,%1,%2,%3}, {%4,%5,%6,%7}, {%8,%9}, {%0,%1,%2,%3};\n"
        : "+f"(c[0]), "+f"(c[1]), "+f"(c[2]), "+f"(c[3])
        : "r"(a0), "r"(a1), "r"(a2), "r"(a3), "r"(b0), "r"(b1));
}

__device__ __forceinline__ void split2(float v, bf16& h, bf16& l) {
    h = __float2bfloat16(v);
    l = __float2bfloat16(v - __bfloat162float(h));
}

// ===========================================================================
// fp32 -> bf16 hi/lo elementwise split
// ===========================================================================
__global__ __launch_bounds__(256) void split_a(
    const float* __restrict__ A, bf16* __restrict__ H, bf16* __restrict__ L, int n)
{
    int idx = (blockIdx.x * 256 + threadIdx.x) * 4;
    if (idx >= n) return;
    float4 v = *reinterpret_cast<const float4*>(A + idx);
    bf16 h0, h1, h2, h3, l0, l1, l2, l3;
    split2(v.x, h0, l0); split2(v.y, h1, l1);
    split2(v.z, h2, l2); split2(v.w, h3, l3);
    __nv_bfloat162 hp0{h0, h1}, hp1{h2, h3}, lp0{l0, l1}, lp1{l2, l3};
    *reinterpret_cast<__nv_bfloat162*>(H + idx)     = hp0;
    *reinterpret_cast<__nv_bfloat162*>(H + idx + 2) = hp1;
    *reinterpret_cast<__nv_bfloat162*>(L + idx)     = lp0;
    *reinterpret_cast<__nv_bfloat162*>(L + idx + 2) = lp1;
}

// W [K x N] fp32 -> Wt [N x K] bf16 hi/lo (transpose + split)
__global__ void split_wt(const float* __restrict__ W,
                         bf16* __restrict__ Th, bf16* __restrict__ Tl)
{
    __shared__ float t[32][33];
    int n0 = blockIdx.x * 32, k0 = blockIdx.y * 32;
    int tx = threadIdx.x, ty = threadIdx.y;     // (32, 8)
    #pragma unroll
    for (int j = 0; j < 32; j += 8)
        t[ty + j][tx] = W[(size_t)(k0 + ty + j) * DMODEL + n0 + tx];
    __syncthreads();
    #pragma unroll
    for (int j = 0; j < 32; j += 8) {
        float v = t[tx][ty + j];
        bf16 h, l; split2(v, h, l);
        size_t o = (size_t)(n0 + ty + j) * DMODEL + k0 + tx;
        Th[o] = h; Tl[o] = l;
    }
}

// ===========================================================================
// bf16x3 HMMA GEMM: [4096 x 1024] = A[4096 x 1024] @ Bt[1024 x 1024]^T + bias
// BM=128, BN=64, BK=32, 256 thr (8 warps 4x2, warp 32x32).
// mode 0: fp32 C row-major.  mode 1: q/k per-head split.  mode 2: v^T split.
// ===========================================================================
#define GP 40    // smem pitch (32 + 8 bf16): frag LDS banks 20g+t4 -> all 32
__global__ __launch_bounds__(256) void gemm_hmma(
    const bf16* __restrict__ Ah, const bf16* __restrict__ Al,
    const bf16* __restrict__ Bh, const bf16* __restrict__ Bl,
    const float* __restrict__ bias,
    float* __restrict__ Cf, bf16* __restrict__ Ch, bf16* __restrict__ Cl,
    int mode)
{
    __shared__ bf16 Ahs[128 * GP], Als[128 * GP];
    __shared__ bf16 Bhs[64 * GP],  Bls[64 * GP];

    const int tid = threadIdx.x, lane = tid & 31, wid = tid >> 5;
    const int g = lane >> 2, t4 = lane & 3;
    const int warpM = wid >> 1, warpN = wid & 1;
    const int bm = blockIdx.y * 128, bn = blockIdx.x * 64;

    float acc[2][4][4] = {};

    for (int k0 = 0; k0 < DMODEL; k0 += 32) {
        #pragma unroll
        for (int it = 0; it < 2; it++) {              // A: 128 rows x 4 uint4
            int f = it * 256 + tid;
            int r = f >> 2, c = (f & 3) << 3;
            size_t go = (size_t)(bm + r) * DMODEL + k0 + c;
            *reinterpret_cast<uint4*>(&Ahs[r * GP + c]) = *reinterpret_cast<const uint4*>(Ah + go);
            *reinterpret_cast<uint4*>(&Als[r * GP + c]) = *reinterpret_cast<const uint4*>(Al + go);
        }
        {                                              // B: 64 rows x 4 uint4
            int r = tid >> 2, c = (tid & 3) << 3;
            size_t go = (size_t)(bn + r) * DMODEL + k0 + c;
            *reinterpret_cast<uint4*>(&Bhs[r * GP + c]) = *reinterpret_cast<const uint4*>(Bh + go);
            *reinterpret_cast<uint4*>(&Bls[r * GP + c]) = *reinterpret_cast<const uint4*>(Bl + go);
        }
        __syncthreads();

        #pragma unroll
        for (int ks = 0; ks < 32; ks += 16) {
            uint32_t ah[2][4], al[2][4], bh[4][2], bl[4][2];
            #pragma unroll
            for (int i = 0; i < 2; i++) {
                int mb = warpM * 32 + i * 16;
                int o0 = (mb + g) * GP + ks + 2 * t4, o1 = (mb + g + 8) * GP + ks + 2 * t4;
                ah[i][0] = *reinterpret_cast<uint32_t*>(&Ahs[o0]);
                ah[i][1] = *reinterpret_cast<uint32_t*>(&Ahs[o1]);
                ah[i][2] = *reinterpret_cast<uint32_t*>(&Ahs[o0 + 8]);
                ah[i][3] = *reinterpret_cast<uint32_t*>(&Ahs[o1 + 8]);
                al[i][0] = *reinterpret_cast<uint32_t*>(&Als[o0]);
                al[i][1] = *reinterpret_cast<uint32_t*>(&Als[o1]);
                al[i][2] = *reinterpret_cast<uint32_t*>(&Als[o0 + 8]);
                al[i][3] = *reinterpret_cast<uint32_t*>(&Als[o1 + 8]);
            }
            #pragma unroll
            for (int j = 0; j < 4; j++) {
                int o = (warpN * 32 + j * 8 + g) * GP + ks + 2 * t4;
                bh[j][0] = *reinterpret_cast<uint32_t*>(&Bhs[o]);
                bh[j][1] = *reinterpret_cast<uint32_t*>(&Bhs[o + 8]);
                bl[j][0] = *reinterpret_cast<uint32_t*>(&Bls[o]);
                bl[j][1] = *reinterpret_cast<uint32_t*>(&Bls[o + 8]);
            }
            #pragma unroll
            for (int i = 0; i < 2; i++)
                #pragma unroll
                for (int j = 0; j < 4; j++) {
                    mma_bf16(acc[i][j], ah[i][0], ah[i][1], ah[i][2], ah[i][3], bh[j][0], bh[j][1]);
                    mma_bf16(acc[i][j], ah[i][0], ah[i][1], ah[i][2], ah[i][3], bl[j][0], bl[j][1]);
                    mma_bf16(acc[i][j], al[i][0], al[i][1], al[i][2], al[i][3], bh[j][0], bh[j][1]);
                }
        }
        __syncthreads();
    }

    const int h = bn >> 6;                       // BN=64: one head per block-col
    #pragma unroll
    for (int i = 0; i < 2; i++) {
        int r0 = bm + warpM * 32 + i * 16 + g;   // and r0+8
        #pragma unroll
        for (int j = 0; j < 4; j++) {
            int nl = warpN * 32 + j * 8 + 2 * t4;     // local col 0..63
            float bia0 = bias[bn + nl], bia1 = bias[bn + nl + 1];
            float v00 = acc[i][j][0] + bia0, v01 = acc[i][j][1] + bia1;
            float v10 = acc[i][j][2] + bia0, v11 = acc[i][j][3] + bia1;
            if (mode == 0) {
                Cf[(size_t)r0 * DMODEL + bn + nl]             = v00;
                Cf[(size_t)r0 * DMODEL + bn + nl + 1]         = v01;
                Cf[(size_t)(r0 + 8) * DMODEL + bn + nl]       = v10;
                Cf[(size_t)(r0 + 8) * DMODEL + bn + nl + 1]   = v11;
            } else if (mode == 1) {
                int s0 = r0 >> 2, b0 = r0 & 3;
                int s1 = (r0 + 8) >> 2, b1 = (r0 + 8) & 3;
                size_t o0 = ((size_t)(h * 4 + b0) * SEQ + s0) * DK + nl;
                size_t o1 = ((size_t)(h * 4 + b1) * SEQ + s1) * DK + nl;
                bf16 hh, ll;
                split2(v00, hh, ll); Ch[o0] = hh;     Cl[o0] = ll;
                split2(v01, hh, ll); Ch[o0 + 1] = hh; Cl[o0 + 1] = ll;
                split2(v10, hh, ll); Ch[o1] = hh;     Cl[o1] = ll;
                split2(v11, hh, ll); Ch[o1 + 1] = hh; Cl[o1 + 1] = ll;
            } else {
                int s0 = r0 >> 2, b0 = r0 & 3;
                int s1 = (r0 + 8) >> 2, b1 = (r0 + 8) & 3;
                size_t o0 = ((size_t)(h * 4 + b0) * DV + nl) * SEQ + s0;
                size_t o1 = ((size_t)(h * 4 + b1) * DV + nl) * SEQ + s1;
                bf16 hh, ll;
                split2(v00, hh, ll); Ch[o0] = hh;        Cl[o0] = ll;
                split2(v01, hh, ll); Ch[o0 + SEQ] = hh;  Cl[o0 + SEQ] = ll;
                split2(v10, hh, ll); Ch[o1] = hh;        Cl[o1] = ll;
                split2(v11, hh, ll); Ch[o1 + SEQ] = hh;  Cl[o1 + SEQ] = ll;
            }
        }
    }
}

// ===========================================================================
// Logits: per hb, 64x64 tile, K=64. 128 thr (4 warps 2x2, warp 32x32).
// ===========================================================================
#define LP 72    // pitch 64+8: frag banks 36g+t4 -> all 32
__global__ __launch_bounds__(128) void logits_hmma(float* __restrict__ attn)
{
    __shared__ bf16 Qhs[64 * LP], Qls[64 * LP], Khs[64 * LP], Kls[64 * LP];

    const int tid = threadIdx.x, lane = tid & 31, wid = tid >> 5;
    const int g = lane >> 2, t4 = lane & 3;
    const int warpM = wid >> 1, warpN = wid & 1;
    const int hb = blockIdx.z;
    const int s0 = blockIdx.y * 64, t0 = blockIdx.x * 64;

    const bf16* qhb = g_qh + (size_t)hb * SEQ * DK;
    const bf16* qlb = g_ql + (size_t)hb * SEQ * DK;
    const bf16* khb = g_kh + (size_t)hb * SEQ * DK;
    const bf16* klb = g_kl + (size_t)hb * SEQ * DK;

    #pragma unroll
    for (int it = 0; it < 4; it++) {          // 64 rows x 8 uint4, 128 thr
        int f = it * 128 + tid;
        int r = f >> 3, c = (f & 7) << 3;
        *reinterpret_cast<uint4*>(&Qhs[r * LP + c]) =
            *reinterpret_cast<const uint4*>(qhb + (size_t)(s0 + r) * DK + c);
        *reinterpret_cast<uint4*>(&Qls[r * LP + c]) =
            *reinterpret_cast<const uint4*>(qlb + (size_t)(s0 + r) * DK + c);
        *reinterpret_cast<uint4*>(&Khs[r * LP + c]) =
            *reinterpret_cast<const uint4*>(khb + (size_t)(t0 + r) * DK + c);
        *reinterpret_cast<uint4*>(&Kls[r * LP + c]) =
            *reinterpret_cast<const uint4*>(klb + (size_t)(t0 + r) * DK + c);
    }
    __syncthreads();

    float acc[2][4][4] = {};
    #pragma unroll
    for (int ks = 0; ks < 64; ks += 16) {
        uint32_t ah[2][4], al[2][4], bh[4][2], bl[4][2];
        #pragma unroll
        for (int i = 0; i < 2; i++) {
            int mb = warpM * 32 + i * 16;
            int o0 = (mb + g) * LP + ks + 2 * t4, o1 = (mb + g + 8) * LP + ks + 2 * t4;
            ah[i][0] = *reinterpret_cast<uint32_t*>(&Qhs[o0]);
            ah[i][1] = *reinterpret_cast<uint32_t*>(&Qhs[o1]);
            ah[i][2] = *reinterpret_cast<uint32_t*>(&Qhs[o0 + 8]);
            ah[i][3] = *reinterpret_cast<uint32_t*>(&Qhs[o1 + 8]);
            al[i][0] = *reinterpret_cast<uint32_t*>(&Qls[o0]);
            al[i][1] = *reinterpret_cast<uint32_t*>(&Qls[o1]);
            al[i][2] = *reinterpret_cast<uint32_t*>(&Qls[o0 + 8]);
            al[i][3] = *reinterpret_cast<uint32_t*>(&Qls[o1 + 8]);
        }
        #pragma unroll
        for (int j = 0; j < 4; j++) {
            int o = (warpN * 32 + j * 8 + g) * LP + ks + 2 * t4;
            bh[j][0] = *reinterpret_cast<uint32_t*>(&Khs[o]);
            bh[j][1] = *reinterpret_cast<uint32_t*>(&Khs[o + 8]);
            bl[j][0] = *reinterpret_cast<uint32_t*>(&Kls[o]);
            bl[j][1] = *reinterpret_cast<uint32_t*>(&Kls[o + 8]);
        }
        #pragma unroll
        for (int i = 0; i < 2; i++)
            #pragma unroll
            for (int j = 0; j < 4; j++) {
                mma_bf16(acc[i][j], ah[i][0], ah[i][1], ah[i][2], ah[i][3], bh[j][0], bh[j][1]);
                mma_bf16(acc[i][j], ah[i][0], ah[i][1], ah[i][2], ah[i][3], bl[j][0], bl[j][1]);
                mma_bf16(acc[i][j], al[i][0], al[i][1], al[i][2], al[i][3], bh[j][0], bh[j][1]);
            }
    }

    float* out = attn + ((size_t)hb * SEQ + s0) * SEQ + t0;
    const float sc = 0.125f;
    #pragma unroll
    for (int i = 0; i < 2; i++) {
        int r0 = warpM * 32 + i * 16 + g;
        #pragma unroll
        for (int j = 0; j < 4; j++) {
            int col = warpN * 32 + j * 8 + 2 * t4;
            float2 v0 = { acc[i][j][0] * sc, acc[i][j][1] * sc };
            float2 v1 = { acc[i][j][2] * sc, acc[i][j][3] * sc };
            *reinterpret_cast<float2*>(out + (size_t)r0 * SEQ + col) = v0;
            *reinterpret_cast<float2*>(out + (size_t)(r0 + 8) * SEQ + col) = v1;
        }
    }
}

// ===========================================================================
// In-place row softmax over 1024. One block (256 thr) per row.
// ===========================================================================
__global__ __launch_bounds__(256) void softmax_kernel(float* __restrict__ attn)
{
    float* p = attn + (size_t)blockIdx.x * 1024;
    const int tid = threadIdx.x;

    float4 v = *reinterpret_cast<const float4*>(p + tid * 4);
    float m = fmaxf(fmaxf(v.x, v.y), fmaxf(v.z, v.w));
    #pragma unroll
    for (int o = 16; o; o >>= 1) m = fmaxf(m, __shfl_xor_sync(0xffffffffu, m, o));

    __shared__ float red[8];
    if ((tid & 31) == 0) red[tid >> 5] = m;
    __syncthreads();
    float bm = red[0];
    #pragma unroll
    for (int w = 1; w < 8; w++) bm = fmaxf(bm, red[w]);

    v.x = __expf(v.x - bm); v.y = __expf(v.y - bm);
    v.z = __expf(v.z - bm); v.w = __expf(v.w - bm);
    float s = (v.x + v.y) + (v.z + v.w);
    #pragma unroll
    for (int o = 16; o; o >>= 1) s += __shfl_xor_sync(0xffffffffu, s, o);

    __syncthreads();
    if ((tid & 31) == 0) red[tid >> 5] = s;
    __syncthreads();
    float tot = ((red[0] + red[1]) + (red[2] + red[3])) +
                ((red[4] + red[5]) + (red[6] + red[7]));
    float inv = 1.0f / tot;

    v.x *= inv; v.y *= inv; v.z *= inv; v.w *= inv;
    *reinterpret_cast<float4*>(p + tid * 4) = v;
}

// ===========================================================================
// AV: ctx_hb = P_hb (1024x1024 fp32) @ V_hb. P split on the fly.
// BM=128(s), BN=64(dv), BK=32(t). 256 thr. Output ctx hi/lo [ROWS][1024].
// ===========================================================================
__global__ __launch_bounds__(256) void av_hmma(const float* __restrict__ attn)
{
    __shared__ bf16 Phs[128 * GP], Pls[128 * GP];
    __shared__ bf16 Vhs[64 * GP],  Vls[64 * GP];

    const int tid = threadIdx.x, lane = tid & 31, wid = tid >> 5;
    const int g = lane >> 2, t4 = lane & 3;
    const int warpM = wid >> 1, warpN = wid & 1;
    const int hb = blockIdx.y;
    const int s0 = blockIdx.x * 128;
    const int h = hb >> 2, b = hb & 3;

    const float* P = attn + (size_t)hb * SEQ * SEQ;
    const bf16* vhb = g_vth + (size_t)hb * DV * SEQ;
    const bf16* vlb = g_vtl + (size_t)hb * DV * SEQ;

    float acc[2][4][4] = {};

    for (int k0 = 0; k0 < SEQ; k0 += 32) {
        #pragma unroll
        for (int it = 0; it < 4; it++) {          // P: 128 rows x 8 float4
            int f = it * 256 + tid;
            int r = f >> 3, c = (f & 7) << 2;
            float4 pv = *reinterpret_cast<const float4*>(P + (size_t)(s0 + r) * SEQ + k0 + c);
            bf16 h0, h1, h2, h3, l0, l1, l2, l3;
            split2(pv.x, h0, l0); split2(pv.y, h1, l1);
            split2(pv.z, h2, l2); split2(pv.w, h3, l3);
            __nv_bfloat162 hp0{h0, h1}, hp1{h2, h3}, lp0{l0, l1}, lp1{l2, l3};
            int o = r * GP + c;
            *reinterpret_cast<__nv_bfloat162*>(&Phs[o])     = hp0;
            *reinterpret_cast<__nv_bfloat162*>(&Phs[o + 2]) = hp1;
            *reinterpret_cast<__nv_bfloat162*>(&Pls[o])     = lp0;
            *reinterpret_cast<__nv_bfloat162*>(&Pls[o + 2]) = lp1;
        }
        {                                          // V: 64 rows x 4 uint4
            int r = tid >> 2, c = (tid & 3) << 3;
            size_t go = (size_t)r * SEQ + k0 + c;
            *reinterpret_cast<uint4*>(&Vhs[r * GP + c]) = *reinterpret_cast<const uint4*>(vhb + go);
            *reinterpret_cast<uint4*>(&Vls[r * GP + c]) = *reinterpret_cast<const uint4*>(vlb + go);
        }
        __syncthreads();

        #pragma unroll
        for (int ks = 0; ks < 32; ks += 16) {
            uint32_t ah[2][4], al[2][4], bh[4][2], bl[4][2];
            #pragma unroll
            for (int i = 0; i < 2; i++) {
                int mb = warpM * 32 + i * 16;
                int o0 = (mb + g) * GP + ks + 2 * t4, o1 = (mb + g + 8) * GP + ks + 2 * t4;
                ah[i][0] = *reinterpret_cast<uint32_t*>(&Phs[o0]);
                ah[i][1] = *reinterpret_cast<uint32_t*>(&Phs[o1]);
                ah[i][2] = *reinterpret_cast<uint32_t*>(&Phs[o0 + 8]);
                ah[i][3] = *reinterpret_cast<uint32_t*>(&Phs[o1 + 8]);
                al[i][0] = *reinterpret_cast<uint32_t*>(&Pls[o0]);
                al[i][1] = *reinterpret_cast<uint32_t*>(&Pls[o1]);
                al[i][2] = *reinterpret_cast<uint32_t*>(&Pls[o0 + 8]);
                al[i][3] = *reinterpret_cast<uint32_t*>(&Pls[o1 + 8]);
            }
            #pragma unroll
            for (int j = 0; j < 4; j++) {
                int o = (warpN * 32 + j * 8 + g) * GP + ks + 2 * t4;
                bh[j][0] = *reinterpret_cast<uint32_t*>(&Vhs[o]);
                bh[j][1] = *reinterpret_cast<uint32_t*>(&Vhs[o + 8]);
                bl[j][0] = *reinterpret_cast<uint32_t*>(&Vls[o]);
                bl[j][1] = *reinterpret_cast<uint32_t*>(&Vls[o + 8]);
            }
            #pragma unroll
            for (int i = 0; i < 2; i++)
                #pragma unroll
                for (int j = 0; j < 4; j++) {
                    mma_bf16(acc[i][j], ah[i][0], ah[i][1], ah[i][2], ah[i][3], bh[j][0], bh[j][1]);
                    mma_bf16(acc[i][j], ah[i][0], ah[i][1], ah[i][2], ah[i][3], bl[j][0], bl[j][1]);
                    mma_bf16(acc[i][j], al[i][0], al[i][1], al[i][2], al[i][3], bh[j][0], bh[j][1]);
                }
        }
        __syncthreads();
    }

    // ctx row = global_s*4 + b, col = h*64 + dv
    #pragma unroll
    for (int i = 0; i < 2; i++) {
        int sA = s0 + warpM * 32 + i * 16 + g;       // and sA+8
        #pragma unroll
        for (int j = 0; j < 4; j++) {
            int dv = warpN * 32 + j * 8 + 2 * t4;
            size_t o0 = ((size_t)sA * 4 + b) * DMODEL + h * 64 + dv;
            size_t o1 = ((size_t)(sA + 8) * 4 + b) * DMODEL + h * 64 + dv;
            bf16 hh, ll;
            split2(acc[i][j][0], hh, ll); g_cth[o0] = hh;     g_ctl[o0] = ll;
            split2(acc[i][j][1], hh, ll); g_cth[o0 + 1] = hh; g_ctl[o0 + 1] = ll;
            split2(acc[i][j][2], hh, ll); g_cth[o1] = hh;     g_ctl[o1] = ll;
            split2(acc[i][j][3], hh, ll); g_cth[o1 + 1] = hh; g_ctl[o1 + 1] = ll;
        }
    }
}

// ===========================================================================
extern "C" void kernel_launch(void* const* d_in, const int* in_sizes, int n_in,
                              void* d_out, int out_size)
{
    const float* query = (const float*)d_in[0];
    const float* key_  = (const float*)d_in[1];
    const float* value = (const float*)d_in[2];
    const float* Wq = (const float*)d_in[3];
    const float* bq = (const float*)d_in[4];
    const float* Wk = (const float*)d_in[5];
    const float* bk = (const float*)d_in[6];
    const float* Wv = (const float*)d_in[7];
    const float* bv = (const float*)d_in[8];
    const float* Wo = (const float*)d_in[9];
    const float* bo = (const float*)d_in[10];

    float* out  = (float*)d_out;                   // (S, B, 1024)
    float* attn = out + (size_t)ROWS * DOUT;       // (H, B, S, S)

    bf16 *qih, *qil, *kih, *kil, *vih, *vil, *wh, *wl;
    bf16 *qh, *ql, *kh, *kl, *vth, *vtl, *cth, *ctl;
    cudaGetSymbolAddress((void**)&qih, s_qi_h); cudaGetSymbolAddress((void**)&qil, s_qi_l);
    cudaGetSymbolAddress((void**)&kih, s_ki_h); cudaGetSymbolAddress((void**)&kil, s_ki_l);
    cudaGetSymbolAddress((void**)&vih, s_vi_h); cudaGetSymbolAddress((void**)&vil, s_vi_l);
    cudaGetSymbolAddress((void**)&wh,  s_w_h);  cudaGetSymbolAddress((void**)&wl,  s_w_l);
    cudaGetSymbolAddress((void**)&qh,  g_qh);   cudaGetSymbolAddress((void**)&ql,  g_ql);
    cudaGetSymbolAddress((void**)&kh,  g_kh);   cudaGetSymbolAddress((void**)&kl,  g_kl);
    cudaGetSymbolAddress((void**)&vth, g_vth);  cudaGetSymbolAddress((void**)&vtl, g_vtl);
    cudaGetSymbolAddress((void**)&cth, g_cth);  cudaGetSymbolAddress((void**)&ctl, g_ctl);
    const size_t WSZ = (size_t)DMODEL * DMODEL;

    const int NEL = ROWS * DMODEL;
    const int splitGrid = NEL / 4 / 256;
    dim3 wtGrid(32, 32), wtBlk(32, 8);
    dim3 gemmGrid(DMODEL / 64, ROWS / 128);        // (16, 32)

    split_a<<<splitGrid, 256>>>(query, qih, qil, NEL);
    split_a<<<splitGrid, 256>>>(key_,  kih, kil, NEL);
    split_a<<<splitGrid, 256>>>(value, vih, vil, NEL);
    split_wt<<<wtGrid, wtBlk>>>(Wq, wh + 0 * WSZ, wl + 0 * WSZ);
    split_wt<<<wtGrid, wtBlk>>>(Wk, wh + 1 * WSZ, wl + 1 * WSZ);
    split_wt<<<wtGrid, wtBlk>>>(Wv, wh + 2 * WSZ, wl + 2 * WSZ);
    split_wt<<<wtGrid, wtBlk>>>(Wo, wh + 3 * WSZ, wl + 3 * WSZ);

    gemm_hmma<<<gemmGrid, 256>>>(qih, qil, wh + 0 * WSZ, wl + 0 * WSZ, bq,
                                 nullptr, qh, ql, 1);
    gemm_hmma<<<gemmGrid, 256>>>(kih, kil, wh + 1 * WSZ, wl + 1 * WSZ, bk,
                                 nullptr, kh, kl, 1);
    gemm_hmma<<<gemmGrid, 256>>>(vih, vil, wh + 2 * WSZ, wl + 2 * WSZ, bv,
                                 nullptr, vth, vtl, 2);

    dim3 gLog(SEQ / 64, SEQ / 64, HB);             // (16, 16, 64)
    logits_hmma<<<gLog, 128>>>(attn);

    softmax_kernel<<<HB * SEQ, 256>>>(attn);

    dim3 gAv(SEQ / 128, HB);                       // (8, 64)
    av_hmma<<<gAv, 256>>>(attn);

    gemm_hmma<<<gemmGrid, 256>>>(cth, ctl, wh + 3 * WSZ, wl + 3 * WSZ, bo,
                                 out, nullptr, nullptr, 0);
}

// round 5
// speedup vs baseline: 1.9726x; 1.0975x over previous
#include <cuda_runtime.h>
#include <cuda_bf16.h>
#include <cstdint>

#define SEQ    1024
#define BATCH  4
#define DMODEL 1024
#define NH     16
#define DK     64
#define DV     64
#define DOUT   1024
#define ROWS   (SEQ * BATCH)      // 4096
#define HB     (NH * BATCH)       // 64

typedef __nv_bfloat16 bf16;

// input splits: [ROWS][1024] hi/lo
__device__ bf16 s_qi_h[ROWS * DMODEL], s_qi_l[ROWS * DMODEL];
__device__ bf16 s_ki_h[ROWS * DMODEL], s_ki_l[ROWS * DMODEL];
__device__ bf16 s_vi_h[ROWS * DMODEL], s_vi_l[ROWS * DMODEL];
// transposed weight splits: [N][K]
__device__ bf16 s_w_h[4][DMODEL * DMODEL], s_w_l[4][DMODEL * DMODEL];
// per-head projections: q,k: [hb][s][64]; vt: [hb][dv][s]
__device__ bf16 g_qh[HB * SEQ * DK], g_ql[HB * SEQ * DK];
__device__ bf16 g_kh[HB * SEQ * DK], g_kl[HB * SEQ * DK];
__device__ bf16 g_vth[HB * DV * SEQ], g_vtl[HB * DV * SEQ];
// context splits: [ROWS][1024]
__device__ bf16 g_cth[ROWS * DMODEL], g_ctl[ROWS * DMODEL];

// m16n8k16 bf16 mma, fp32 accum
__device__ __forceinline__ void mma_bf16(float* c,
    uint32_t a0, uint32_t a1, uint32_t a2, uint32_t a3, uint32_t b0, uint32_t b1)
{
    asm volatile(
        "mma.sync.aligned.m16n8k16.row.col.f32.bf16.bf16.f32 "
        "{%0,%1,%2,%3}, {%4,%5,%6,%7}, {%8,%9}, {%0,%1,%2,%3};\n"
        : "+f"(c[0]), "+f"(c[1]), "+f"(c[2]), "+f"(c[3])
        : "r"(a0), "r"(a1), "r"(a2), "r"(a3), "r"(b0), "r"(b1));
}

__device__ __forceinline__ void split2(float v, bf16& h, bf16& l) {
    h = __float2bfloat16(v);
    l = __float2bfloat16(v - __bfloat162float(h));
}

__device__ __forceinline__ uint32_t smem_u32(const void* p) {
    uint32_t a;
    asm("{ .reg .u64 t; cvta.to.shared.u64 t, %1; cvt.u32.u64 %0, t; }" : "=r"(a) : "l"(p));
    return a;
}
__device__ __forceinline__ void cp16(uint32_t s, const void* g) {
    asm volatile("cp.async.cg.shared.global [%0], [%1], 16;" :: "r"(s), "l"(g));
}
#define CP_COMMIT() asm volatile("cp.async.commit_group;" ::: "memory")
#define CP_WAIT(n)  asm volatile("cp.async.wait_group %0;" :: "n"(n) : "memory")

__device__ __forceinline__ void ldm_x4(uint32_t* r, uint32_t addr) {
    asm volatile("ldmatrix.sync.aligned.m8n8.x4.shared.b16 {%0,%1,%2,%3}, [%4];"
                 : "=r"(r[0]), "=r"(r[1]), "=r"(r[2]), "=r"(r[3]) : "r"(addr));
}

// ===========================================================================
// fp32 -> bf16 hi/lo elementwise split
// ===========================================================================
__global__ __launch_bounds__(256) void split_a(
    const float* __restrict__ A, bf16* __restrict__ H, bf16* __restrict__ L, int n)
{
    int idx = (blockIdx.x * 256 + threadIdx.x) * 4;
    if (idx >= n) return;
    float4 v = *reinterpret_cast<const float4*>(A + idx);
    bf16 h0, h1, h2, h3, l0, l1, l2, l3;
    split2(v.x, h0, l0); split2(v.y, h1, l1);
    split2(v.z, h2, l2); split2(v.w, h3, l3);
    __nv_bfloat162 hp0{h0, h1}, hp1{h2, h3}, lp0{l0, l1}, lp1{l2, l3};
    *reinterpret_cast<__nv_bfloat162*>(H + idx)     = hp0;
    *reinterpret_cast<__nv_bfloat162*>(H + idx + 2) = hp1;
    *reinterpret_cast<__nv_bfloat162*>(L + idx)     = lp0;
    *reinterpret_cast<__nv_bfloat162*>(L + idx + 2) = lp1;
}

// W [K x N] fp32 -> Wt [N x K] bf16 hi/lo (transpose + split)
__global__ void split_wt(const float* __restrict__ W,
                         bf16* __restrict__ Th, bf16* __restrict__ Tl)
{
    __shared__ float t[32][33];
    int n0 = blockIdx.x * 32, k0 = blockIdx.y * 32;
    int tx = threadIdx.x, ty = threadIdx.y;     // (32, 8)
    #pragma unroll
    for (int j = 0; j < 32; j += 8)
        t[ty + j][tx] = W[(size_t)(k0 + ty + j) * DMODEL + n0 + tx];
    __syncthreads();
    #pragma unroll
    for (int j = 0; j < 32; j += 8) {
        float v = t[tx][ty + j];
        bf16 h, l; split2(v, h, l);
        size_t o = (size_t)(n0 + ty + j) * DMODEL + k0 + tx;
        Th[o] = h; Tl[o] = l;
    }
}

// ===========================================================================
// bf16x3 HMMA GEMM, cp.async 2-stage + ldmatrix.
// C[4096 x 1024] = A[4096 x 1024] @ Bt[1024 x 1024]^T + bias
// BM=128, BN=64, BK=64. 128 thr (4 warps 2x2, warp 64x32).
// mode 0: fp32 C. mode 1: q/k per-head split. mode 2: v^T split.
// ===========================================================================
#define GEMM_PITCH 72                          // bf16; 144B rows -> ldmatrix conflict-free
#define ST_AH 0
#define ST_AL (128 * GEMM_PITCH * 2)           // 18432
#define ST_BH (2 * 128 * GEMM_PITCH * 2)       // 36864
#define ST_BL (ST_BH + 64 * GEMM_PITCH * 2)    // 46080
#define STAGE_B (ST_BL + 64 * GEMM_PITCH * 2)  // 55296
#define GEMM_SMEM (2 * STAGE_B)                // 110592

__global__ __launch_bounds__(128) void gemm_hmma(
    const bf16* __restrict__ Ah, const bf16* __restrict__ Al,
    const bf16* __restrict__ Bh, const bf16* __restrict__ Bl,
    const float* __restrict__ bias,
    float* __restrict__ Cf, bf16* __restrict__ Ch, bf16* __restrict__ Cl,
    int mode)
{
    extern __shared__ char smem[];
    const uint32_t sb = smem_u32(smem);

    const int tid = threadIdx.x, lane = tid & 31, wid = tid >> 5;
    const int g = lane >> 2, t4 = lane & 3;
    const int warpM = wid >> 1, warpN = wid & 1;
    const int bm = blockIdx.y * 128, bn = blockIdx.x * 64;

    // ldmatrix lane addressing components
    const int lrow = lane & 15;                 // row within 16
    const int lcol = (lane >> 4) << 3;          // 0 or 8 (k-half)

    float acc[4][4][4] = {};
    const int nch = DMODEL / 64;                // 16

    // ---- stage loader: 24 cp.async per thread ----
    auto load_stage = [&](int stg, int k0) {
        const uint32_t base = sb + stg * STAGE_B;
        #pragma unroll
        for (int m = 0; m < 8; m++) {           // A: 1024 chunks / 128 thr
            int q = m * 128 + tid;
            int r = q >> 3, c = q & 7;
            size_t go = (size_t)(bm + r) * DMODEL + k0 + c * 8;
            uint32_t so = (uint32_t)(r * GEMM_PITCH + c * 8) * 2;
            cp16(base + ST_AH + so, Ah + go);
            cp16(base + ST_AL + so, Al + go);
        }
        #pragma unroll
        for (int m = 0; m < 4; m++) {           // B: 512 chunks / 128 thr
            int q = m * 128 + tid;
            int r = q >> 3, c = q & 7;
            size_t go = (size_t)(bn + r) * DMODEL + k0 + c * 8;
            uint32_t so = (uint32_t)(r * GEMM_PITCH + c * 8) * 2;
            cp16(base + ST_BH + so, Bh + go);
            cp16(base + ST_BL + so, Bl + go);
        }
    };

    load_stage(0, 0);
    CP_COMMIT();

    for (int c = 0; c < nch; c++) {
        if (c + 1 < nch) { load_stage((c + 1) & 1, (c + 1) * 64); CP_COMMIT(); CP_WAIT(1); }
        else             { CP_WAIT(0); }
        __syncthreads();

        const uint32_t base = sb + (c & 1) * STAGE_B;
        #pragma unroll
        for (int ks = 0; ks < 64; ks += 16) {
            uint32_t ah[4][4], al[4][4], bh[2][4], bl[2][4];
            #pragma unroll
            for (int i = 0; i < 4; i++) {
                uint32_t off = (uint32_t)((warpM * 64 + i * 16 + lrow) * GEMM_PITCH + ks + lcol) * 2;
                ldm_x4(ah[i], base + ST_AH + off);
                ldm_x4(al[i], base + ST_AL + off);
            }
            #pragma unroll
            for (int jj = 0; jj < 2; jj++) {
                uint32_t off = (uint32_t)((warpN * 32 + jj * 16 + lrow) * GEMM_PITCH + ks + lcol) * 2;
                ldm_x4(bh[jj], base + ST_BH + off);
                ldm_x4(bl[jj], base + ST_BL + off);
            }
            #pragma unroll
            for (int i = 0; i < 4; i++)
                #pragma unroll
                for (int j = 0; j < 4; j++) {
                    int jj = j >> 1, p = j & 1;
                    mma_bf16(acc[i][j], ah[i][0], ah[i][1], ah[i][2], ah[i][3],
                             bh[jj][p], bh[jj][p + 2]);
                    mma_bf16(acc[i][j], ah[i][0], ah[i][1], ah[i][2], ah[i][3],
                             bl[jj][p], bl[jj][p + 2]);
                    mma_bf16(acc[i][j], al[i][0], al[i][1], al[i][2], al[i][3],
                             bh[jj][p], bh[jj][p + 2]);
                }
        }
        __syncthreads();
    }

    const int h = bn >> 6;
    #pragma unroll
    for (int i = 0; i < 4; i++) {
        int r0 = bm + warpM * 64 + i * 16 + g;       // and r0+8
        #pragma unroll
        for (int j = 0; j < 4; j++) {
            int nl = warpN * 32 + j * 8 + 2 * t4;
            float bia0 = bias[bn + nl], bia1 = bias[bn + nl + 1];
            float v00 = acc[i][j][0] + bia0, v01 = acc[i][j][1] + bia1;
            float v10 = acc[i][j][2] + bia0, v11 = acc[i][j][3] + bia1;
            if (mode == 0) {
                Cf[(size_t)r0 * DMODEL + bn + nl]           = v00;
                Cf[(size_t)r0 * DMODEL + bn + nl + 1]       = v01;
                Cf[(size_t)(r0 + 8) * DMODEL + bn + nl]     = v10;
                Cf[(size_t)(r0 + 8) * DMODEL + bn + nl + 1] = v11;
            } else if (mode == 1) {
                int s0 = r0 >> 2, b0 = r0 & 3;
                int s1 = (r0 + 8) >> 2, b1 = (r0 + 8) & 3;
                size_t o0 = ((size_t)(h * 4 + b0) * SEQ + s0) * DK + nl;
                size_t o1 = ((size_t)(h * 4 + b1) * SEQ + s1) * DK + nl;
                bf16 hh, ll;
                split2(v00, hh, ll); Ch[o0] = hh;     Cl[o0] = ll;
                split2(v01, hh, ll); Ch[o0 + 1] = hh; Cl[o0 + 1] = ll;
                split2(v10, hh, ll); Ch[o1] = hh;     Cl[o1] = ll;
                split2(v11, hh, ll); Ch[o1 + 1] = hh; Cl[o1 + 1] = ll;
            } else {
                int s0 = r0 >> 2, b0 = r0 & 3;
                int s1 = (r0 + 8) >> 2, b1 = (r0 + 8) & 3;
                size_t o0 = ((size_t)(h * 4 + b0) * DV + nl) * SEQ + s0;
                size_t o1 = ((size_t)(h * 4 + b1) * DV + nl) * SEQ + s1;
                bf16 hh, ll;
                split2(v00, hh, ll); Ch[o0] = hh;        Cl[o0] = ll;
                split2(v01, hh, ll); Ch[o0 + SEQ] = hh;  Cl[o0 + SEQ] = ll;
                split2(v10, hh, ll); Ch[o1] = hh;        Cl[o1] = ll;
                split2(v11, hh, ll); Ch[o1 + SEQ] = hh;  Cl[o1 + SEQ] = ll;
            }
        }
    }
}

// ===========================================================================
// Logits: per hb, 64x64 tile, K=64. 128 thr (4 warps 2x2, warp 32x32).
// ===========================================================================
#define LP 72    // pitch 64+8: frag banks 36g+t4 -> all 32
__global__ __launch_bounds__(128) void logits_hmma(float* __restrict__ attn)
{
    __shared__ bf16 Qhs[64 * LP], Qls[64 * LP], Khs[64 * LP], Kls[64 * LP];

    const int tid = threadIdx.x, lane = tid & 31, wid = tid >> 5;
    const int g = lane >> 2, t4 = lane & 3;
    const int warpM = wid >> 1, warpN = wid & 1;
    const int hb = blockIdx.z;
    const int s0 = blockIdx.y * 64, t0 = blockIdx.x * 64;

    const bf16* qhb = g_qh + (size_t)hb * SEQ * DK;
    const bf16* qlb = g_ql + (size_t)hb * SEQ * DK;
    const bf16* khb = g_kh + (size_t)hb * SEQ * DK;
    const bf16* klb = g_kl + (size_t)hb * SEQ * DK;

    #pragma unroll
    for (int it = 0; it < 4; it++) {
        int f = it * 128 + tid;
        int r = f >> 3, c = (f & 7) << 3;
        *reinterpret_cast<uint4*>(&Qhs[r * LP + c]) =
            *reinterpret_cast<const uint4*>(qhb + (size_t)(s0 + r) * DK + c);
        *reinterpret_cast<uint4*>(&Qls[r * LP + c]) =
            *reinterpret_cast<const uint4*>(qlb + (size_t)(s0 + r) * DK + c);
        *reinterpret_cast<uint4*>(&Khs[r * LP + c]) =
            *reinterpret_cast<const uint4*>(khb + (size_t)(t0 + r) * DK + c);
        *reinterpret_cast<uint4*>(&Kls[r * LP + c]) =
            *reinterpret_cast<const uint4*>(klb + (size_t)(t0 + r) * DK + c);
    }
    __syncthreads();

    float acc[2][4][4] = {};
    #pragma unroll
    for (int ks = 0; ks < 64; ks += 16) {
        uint32_t ah[2][4], al[2][4], bh[4][2], bl[4][2];
        #pragma unroll
        for (int i = 0; i < 2; i++) {
            int mb = warpM * 32 + i * 16;
            int o0 = (mb + g) * LP + ks + 2 * t4, o1 = (mb + g + 8) * LP + ks + 2 * t4;
            ah[i][0] = *reinterpret_cast<uint32_t*>(&Qhs[o0]);
            ah[i][1] = *reinterpret_cast<uint32_t*>(&Qhs[o1]);
            ah[i][2] = *reinterpret_cast<uint32_t*>(&Qhs[o0 + 8]);
            ah[i][3] = *reinterpret_cast<uint32_t*>(&Qhs[o1 + 8]);
            al[i][0] = *reinterpret_cast<uint32_t*>(&Qls[o0]);
            al[i][1] = *reinterpret_cast<uint32_t*>(&Qls[o1]);
            al[i][2] = *reinterpret_cast<uint32_t*>(&Qls[o0 + 8]);
            al[i][3] = *reinterpret_cast<uint32_t*>(&Qls[o1 + 8]);
        }
        #pragma unroll
        for (int j = 0; j < 4; j++) {
            int o = (warpN * 32 + j * 8 + g) * LP + ks + 2 * t4;
            bh[j][0] = *reinterpret_cast<uint32_t*>(&Khs[o]);
            bh[j][1] = *reinterpret_cast<uint32_t*>(&Khs[o + 8]);
            bl[j][0] = *reinterpret_cast<uint32_t*>(&Kls[o]);
            bl[j][1] = *reinterpret_cast<uint32_t*>(&Kls[o + 8]);
        }
        #pragma unroll
        for (int i = 0; i < 2; i++)
            #pragma unroll
            for (int j = 0; j < 4; j++) {
                mma_bf16(acc[i][j], ah[i][0], ah[i][1], ah[i][2], ah[i][3], bh[j][0], bh[j][1]);
                mma_bf16(acc[i][j], ah[i][0], ah[i][1], ah[i][2], ah[i][3], bl[j][0], bl[j][1]);
                mma_bf16(acc[i][j], al[i][0], al[i][1], al[i][2], al[i][3], bh[j][0], bh[j][1]);
            }
    }

    float* out = attn + ((size_t)hb * SEQ + s0) * SEQ + t0;
    const float sc = 0.125f;
    #pragma unroll
    for (int i = 0; i < 2; i++) {
        int r0 = warpM * 32 + i * 16 + g;
        #pragma unroll
        for (int j = 0; j < 4; j++) {
            int col = warpN * 32 + j * 8 + 2 * t4;
            float2 v0 = { acc[i][j][0] * sc, acc[i][j][1] * sc };
            float2 v1 = { acc[i][j][2] * sc, acc[i][j][3] * sc };
            *reinterpret_cast<float2*>(out + (size_t)r0 * SEQ + col) = v0;
            *reinterpret_cast<float2*>(out + (size_t)(r0 + 8) * SEQ + col) = v1;
        }
    }
}

// ===========================================================================
// In-place row softmax over 1024. One block (256 thr) per row.
// ===========================================================================
__global__ __launch_bounds__(256) void softmax_kernel(float* __restrict__ attn)
{
    float* p = attn + (size_t)blockIdx.x * 1024;
    const int tid = threadIdx.x;

    float4 v = *reinterpret_cast<const float4*>(p + tid * 4);
    float m = fmaxf(fmaxf(v.x, v.y), fmaxf(v.z, v.w));
    #pragma unroll
    for (int o = 16; o; o >>= 1) m = fmaxf(m, __shfl_xor_sync(0xffffffffu, m, o));

    __shared__ float red[8];
    if ((tid & 31) == 0) red[tid >> 5] = m;
    __syncthreads();
    float bm = red[0];
    #pragma unroll
    for (int w = 1; w < 8; w++) bm = fmaxf(bm, red[w]);

    v.x = __expf(v.x - bm); v.y = __expf(v.y - bm);
    v.z = __expf(v.z - bm); v.w = __expf(v.w - bm);
    float s = (v.x + v.y) + (v.z + v.w);
    #pragma unroll
    for (int o = 16; o; o >>= 1) s += __shfl_xor_sync(0xffffffffu, s, o);

    __syncthreads();
    if ((tid & 31) == 0) red[tid >> 5] = s;
    __syncthreads();
    float tot = ((red[0] + red[1]) + (red[2] + red[3])) +
                ((red[4] + red[5]) + (red[6] + red[7]));
    float inv = 1.0f / tot;

    v.x *= inv; v.y *= inv; v.z *= inv; v.w *= inv;
    *reinterpret_cast<float4*>(p + tid * 4) = v;
}

// ===========================================================================
// AV: ctx_hb = P_hb (1024x1024 fp32) @ V_hb. P split on the fly.
// BM=128(s), BN=64(dv), BK=32(t). 256 thr. Output ctx hi/lo [ROWS][1024].
// ===========================================================================
#define GP 40
__global__ __launch_bounds__(256) void av_hmma(const float* __restrict__ attn)
{
    __shared__ bf16 Phs[128 * GP], Pls[128 * GP];
    __shared__ bf16 Vhs[64 * GP],  Vls[64 * GP];

    const int tid = threadIdx.x, lane = tid & 31, wid = tid >> 5;
    const int g = lane >> 2, t4 = lane & 3;
    const int warpM = wid >> 1, warpN = wid & 1;
    const int hb = blockIdx.y;
    const int s0 = blockIdx.x * 128;
    const int h = hb >> 2, b = hb & 3;

    const float* P = attn + (size_t)hb * SEQ * SEQ;
    const bf16* vhb = g_vth + (size_t)hb * DV * SEQ;
    const bf16* vlb = g_vtl + (size_t)hb * DV * SEQ;

    float acc[2][4][4] = {};

    for (int k0 = 0; k0 < SEQ; k0 += 32) {
        #pragma unroll
        for (int it = 0; it < 4; it++) {
            int f = it * 256 + tid;
            int r = f >> 3, c = (f & 7) << 2;
            float4 pv = *reinterpret_cast<const float4*>(P + (size_t)(s0 + r) * SEQ + k0 + c);
            bf16 h0, h1, h2, h3, l0, l1, l2, l3;
            split2(pv.x, h0, l0); split2(pv.y, h1, l1);
            split2(pv.z, h2, l2); split2(pv.w, h3, l3);
            __nv_bfloat162 hp0{h0, h1}, hp1{h2, h3}, lp0{l0, l1}, lp1{l2, l3};
            int o = r * GP + c;
            *reinterpret_cast<__nv_bfloat162*>(&Phs[o])     = hp0;
            *reinterpret_cast<__nv_bfloat162*>(&Phs[o + 2]) = hp1;
            *reinterpret_cast<__nv_bfloat162*>(&Pls[o])     = lp0;
            *reinterpret_cast<__nv_bfloat162*>(&Pls[o + 2]) = lp1;
        }
        {
            int r = tid >> 2, c = (tid & 3) << 3;
            size_t go = (size_t)r * SEQ + k0 + c;
            *reinterpret_cast<uint4*>(&Vhs[r * GP + c]) = *reinterpret_cast<const uint4*>(vhb + go);
            *reinterpret_cast<uint4*>(&Vls[r * GP + c]) = *reinterpret_cast<const uint4*>(vlb + go);
        }
        __syncthreads();

        #pragma unroll
        for (int ks = 0; ks < 32; ks += 16) {
            uint32_t ah[2][4], al[2][4], bh[4][2], bl[4][2];
            #pragma unroll
            for (int i = 0; i < 2; i++) {
                int mb = warpM * 32 + i * 16;
                int o0 = (mb + g) * GP + ks + 2 * t4, o1 = (mb + g + 8) * GP + ks + 2 * t4;
                ah[i][0] = *reinterpret_cast<uint32_t*>(&Phs[o0]);
                ah[i][1] = *reinterpret_cast<uint32_t*>(&Phs[o1]);
                ah[i][2] = *reinterpret_cast<uint32_t*>(&Phs[o0 + 8]);
                ah[i][3] = *reinterpret_cast<uint32_t*>(&Phs[o1 + 8]);
                al[i][0] = *reinterpret_cast<uint32_t*>(&Pls[o0]);
                al[i][1] = *reinterpret_cast<uint32_t*>(&Pls[o1]);
                al[i][2] = *reinterpret_cast<uint32_t*>(&Pls[o0 + 8]);
                al[i][3] = *reinterpret_cast<uint32_t*>(&Pls[o1 + 8]);
            }
            #pragma unroll
            for (int j = 0; j < 4; j++) {
                int o = (warpN * 32 + j * 8 + g) * GP + ks + 2 * t4;
                bh[j][0] = *reinterpret_cast<uint32_t*>(&Vhs[o]);
                bh[j][1] = *reinterpret_cast<uint32_t*>(&Vhs[o + 8]);
                bl[j][0] = *reinterpret_cast<uint32_t*>(&Vls[o]);
                bl[j][1] = *reinterpret_cast<uint32_t*>(&Vls[o + 8]);
            }
            #pragma unroll
            for (int i = 0; i < 2; i++)
                #pragma unroll
                for (int j = 0; j < 4; j++) {
                    mma_bf16(acc[i][j], ah[i][0], ah[i][1], ah[i][2], ah[i][3], bh[j][0], bh[j][1]);
                    mma_bf16(acc[i][j], ah[i][0], ah[i][1], ah[i][2], ah[i][3], bl[j][0], bl[j][1]);
                    mma_bf16(acc[i][j], al[i][0], al[i][1], al[i][2], al[i][3], bh[j][0], bh[j][1]);
                }
        }
        __syncthreads();
    }

    #pragma unroll
    for (int i = 0; i < 2; i++) {
        int sA = s0 + warpM * 32 + i * 16 + g;
        #pragma unroll
        for (int j = 0; j < 4; j++) {
            int dv = warpN * 32 + j * 8 + 2 * t4;
            size_t o0 = ((size_t)sA * 4 + b) * DMODEL + h * 64 + dv;
            size_t o1 = ((size_t)(sA + 8) * 4 + b) * DMODEL + h * 64 + dv;
            bf16 hh, ll;
            split2(acc[i][j][0], hh, ll); g_cth[o0] = hh;     g_ctl[o0] = ll;
            split2(acc[i][j][1], hh, ll); g_cth[o0 + 1] = hh; g_ctl[o0 + 1] = ll;
            split2(acc[i][j][2], hh, ll); g_cth[o1] = hh;     g_ctl[o1] = ll;
            split2(acc[i][j][3], hh, ll); g_cth[o1 + 1] = hh; g_ctl[o1 + 1] = ll;
        }
    }
}

// ===========================================================================
extern "C" void kernel_launch(void* const* d_in, const int* in_sizes, int n_in,
                              void* d_out, int out_size)
{
    const float* query = (const float*)d_in[0];
    const float* key_  = (const float*)d_in[1];
    const float* value = (const float*)d_in[2];
    const float* Wq = (const float*)d_in[3];
    const float* bq = (const float*)d_in[4];
    const float* Wk = (const float*)d_in[5];
    const float* bk = (const float*)d_in[6];
    const float* Wv = (const float*)d_in[7];
    const float* bv = (const float*)d_in[8];
    const float* Wo = (const float*)d_in[9];
    const float* bo = (const float*)d_in[10];

    float* out  = (float*)d_out;
    float* attn = out + (size_t)ROWS * DOUT;

    bf16 *qih, *qil, *kih, *kil, *vih, *vil, *wh, *wl;
    bf16 *qh, *ql, *kh, *kl, *vth, *vtl, *cth, *ctl;
    cudaGetSymbolAddress((void**)&qih, s_qi_h); cudaGetSymbolAddress((void**)&qil, s_qi_l);
    cudaGetSymbolAddress((void**)&kih, s_ki_h); cudaGetSymbolAddress((void**)&kil, s_ki_l);
    cudaGetSymbolAddress((void**)&vih, s_vi_h); cudaGetSymbolAddress((void**)&vil, s_vi_l);
    cudaGetSymbolAddress((void**)&wh,  s_w_h);  cudaGetSymbolAddress((void**)&wl,  s_w_l);
    cudaGetSymbolAddress((void**)&qh,  g_qh);   cudaGetSymbolAddress((void**)&ql,  g_ql);
    cudaGetSymbolAddress((void**)&kh,  g_kh);   cudaGetSymbolAddress((void**)&kl,  g_kl);
    cudaGetSymbolAddress((void**)&vth, g_vth);  cudaGetSymbolAddress((void**)&vtl, g_vtl);
    cudaGetSymbolAddress((void**)&cth, g_cth);  cudaGetSymbolAddress((void**)&ctl, g_ctl);
    const size_t WSZ = (size_t)DMODEL * DMODEL;

    static int smem_set = 0;
    if (!smem_set) {
        cudaFuncSetAttribute(gemm_hmma, cudaFuncAttributeMaxDynamicSharedMemorySize, GEMM_SMEM);
        smem_set = 1;
    }

    const int NEL = ROWS * DMODEL;
    const int splitGrid = NEL / 4 / 256;
    dim3 wtGrid(32, 32), wtBlk(32, 8);
    dim3 gemmGrid(DMODEL / 64, ROWS / 128);        // (16, 32)

    split_a<<<splitGrid, 256>>>(query, qih, qil, NEL);
    split_a<<<splitGrid, 256>>>(key_,  kih, kil, NEL);
    split_a<<<splitGrid, 256>>>(value, vih, vil, NEL);
    split_wt<<<wtGrid, wtBlk>>>(Wq, wh + 0 * WSZ, wl + 0 * WSZ);
    split_wt<<<wtGrid, wtBlk>>>(Wk, wh + 1 * WSZ, wl + 1 * WSZ);
    split_wt<<<wtGrid, wtBlk>>>(Wv, wh + 2 * WSZ, wl + 2 * WSZ);
    split_wt<<<wtGrid, wtBlk>>>(Wo, wh + 3 * WSZ, wl + 3 * WSZ);

    gemm_hmma<<<gemmGrid, 128, GEMM_SMEM>>>(qih, qil, wh + 0 * WSZ, wl + 0 * WSZ, bq,
                                            nullptr, qh, ql, 1);
    gemm_hmma<<<gemmGrid, 128, GEMM_SMEM>>>(kih, kil, wh + 1 * WSZ, wl + 1 * WSZ, bk,
                                            nullptr, kh, kl, 1);
    gemm_hmma<<<gemmGrid, 128, GEMM_SMEM>>>(vih, vil, wh + 2 * WSZ, wl + 2 * WSZ, bv,
                                            nullptr, vth, vtl, 2);

    dim3 gLog(SEQ / 64, SEQ / 64, HB);             // (16, 16, 64)
    logits_hmma<<<gLog, 128>>>(attn);

    softmax_kernel<<<HB * SEQ, 256>>>(attn);

    dim3 gAv(SEQ / 128, HB);                       // (8, 64)
    av_hmma<<<gAv, 256>>>(attn);

    gemm_hmma<<<gemmGrid, 128, GEMM_SMEM>>>(cth, ctl, wh + 3 * WSZ, wl + 3 * WSZ, bo,
                                            out, nullptr, nullptr, 0);
}